// round 15
// baseline (speedup 1.0000x reference)
#include <cuda_runtime.h>
#include <cuda_bf16.h>

typedef unsigned long long u64;
typedef unsigned int u32;

#define E_TOT   10000
#define FREQ    44
#define EB      8
#define NBLK    (E_TOT / EB)               // 1250, exact
#define LN_EPS  1e-5f

#define MLP_BLOCKS  (E_TOT / 8)                     // 1250
#define W3T_BLOCKS  ((FREQ * 32 * 256 + 255) / 256) // 1408

#define GE      64
#define GEB     ((E_TOT + GE - 1) / GE)             // 157

#define STRIDE  272                        // floats per edge-row (e-offset = 16 banks)
#define BUF     (EB * STRIDE)              // 2176 floats per slice buffer

// scratch
__device__ float g_h[E_TOT * 32];
__device__ float g_w3t[FREQ * 32 * 256];            // [f][m][p], p = ci*16+co
__device__ float g_R[(size_t)E_TOT * FREQ * 256];   // [e][f][p]  (~450 MB)

// ---------------------------------------------------------------------------
__device__ __forceinline__ u64 f2fma(u64 a, u64 b, u64 c) {
    u64 d;
    asm("fma.rn.f32x2 %0, %1, %2, %3;" : "=l"(d) : "l"(a), "l"(b), "l"(c));
    return d;
}
__device__ __forceinline__ u64 dup2(float x) {
    u64 d;
    asm("mov.b64 %0, {%1, %1};" : "=l"(d) : "f"(x));
    return d;
}
__device__ __forceinline__ u32 smem_u32(const void* p) {
    u32 a;
    asm("{ .reg .u64 t; cvta.to.shared.u64 t, %1; cvt.u32.u64 %0, t; }" : "=r"(a) : "l"(p));
    return a;
}
__device__ __forceinline__ void cp16(u32 s, const float* g) {
    asm volatile("cp.async.cg.shared.global [%0], [%1], 16;\n" :: "r"(s), "l"(g));
}
__device__ __forceinline__ void cp_commit() {
    asm volatile("cp.async.commit_group;\n");
}
template <int N>
__device__ __forceinline__ void cp_wait() {
    asm volatile("cp.async.wait_group %0;\n" :: "n"(N));
}

// ---------------------------------------------------------------------------
// prep kernel: MLP (first MLP_BLOCKS blocks) + w3 transpose (rest)
// ---------------------------------------------------------------------------
__device__ __forceinline__ float ln_relu_32(float y, float gamma, float beta) {
    float s = y, q = y * y;
    #pragma unroll
    for (int d = 16; d > 0; d >>= 1) {
        s += __shfl_xor_sync(0xffffffffu, s, d);
        q += __shfl_xor_sync(0xffffffffu, q, d);
    }
    float mean = s * (1.0f / 32.0f);
    float var  = q * (1.0f / 32.0f) - mean * mean;
    float r = rsqrtf(var + LN_EPS);
    float v = (y - mean) * r * gamma + beta;
    return fmaxf(v, 0.0f);
}

__global__ void __launch_bounds__(256) prep_kernel(
    const float* __restrict__ inv,
    const float* __restrict__ w1, const float* __restrict__ b1,
    const float* __restrict__ g1, const float* __restrict__ be1,
    const float* __restrict__ w2, const float* __restrict__ b2,
    const float* __restrict__ g2, const float* __restrict__ be2,
    const float* __restrict__ w3)
{
    if (blockIdx.x >= MLP_BLOCKS) {
        int idx = (blockIdx.x - MLP_BLOCKS) * 256 + threadIdx.x;
        if (idx < FREQ * 32 * 256) {
            int p = idx & 255;
            int m = (idx >> 8) & 31;
            int f = idx >> 13;
            int row = (p & 15) * 704 + (p >> 4) * 44 + f;
            g_w3t[idx] = w3[row * 32 + m];
        }
        return;
    }

    __shared__ float w1_s[32 * 16];
    __shared__ float w2_s[32 * 32];
    __shared__ float p_s[6 * 32];

    int tid = threadIdx.x;
    for (int i = tid; i < 512;  i += 256) w1_s[i] = w1[i];
    for (int i = tid; i < 1024; i += 256) w2_s[i] = w2[i];
    if (tid < 32) {
        p_s[tid]       = b1[tid];
        p_s[32  + tid] = g1[tid];
        p_s[64  + tid] = be1[tid];
        p_s[96  + tid] = b2[tid];
        p_s[128 + tid] = g2[tid];
        p_s[160 + tid] = be2[tid];
    }
    __syncthreads();

    int w = tid >> 5;
    int m = tid & 31;
    int e = blockIdx.x * 8 + w;

    float xv = (m < 16) ? inv[e * 16 + m] : 0.0f;

    float y = p_s[m];
    #pragma unroll
    for (int in = 0; in < 16; in++)
        y = fmaf(__shfl_sync(0xffffffffu, xv, in), w1_s[m * 16 + in], y);
    y = ln_relu_32(y, p_s[32 + m], p_s[64 + m]);

    float y2 = p_s[96 + m];
    #pragma unroll
    for (int k = 0; k < 32; k++)
        y2 = fmaf(__shfl_sync(0xffffffffu, y, k), w2_s[m * 32 + k], y2);
    y2 = ln_relu_32(y2, p_s[128 + m], p_s[160 + m]);

    g_h[e * 32 + m] = y2;
}

// ---------------------------------------------------------------------------
// rw GEMM kernel: g_R[e][f][p] = sum_m g_h[e][m] * g_w3t[f][m][p]
// ---------------------------------------------------------------------------
__global__ void __launch_bounds__(256) rw_gemm_kernel()
{
    __shared__ float hs2[32 * 64];    // [m][e]

    const int t   = threadIdx.x;
    const int f   = blockIdx.x % FREQ;
    const int eb0 = (blockIdx.x / FREQ) * GE;

    #pragma unroll
    for (int i = 0; i < 8; i++) {
        int idx = t + i * 256;
        int e = idx >> 5, m = idx & 31;
        hs2[m * 64 + e] = (eb0 + e < E_TOT) ? g_h[(eb0 + e) * 32 + m] : 0.0f;
    }
    __syncthreads();

    const int p0 = (t & 63) * 4;
    const int eg = t >> 6;

    const float* wp = g_w3t + (size_t)f * 8192 + p0;
    const float* hp = hs2 + eg * 16;

    u64 acc[8][4];
    #pragma unroll
    for (int i = 0; i < 8; i++)
        #pragma unroll
        for (int j = 0; j < 4; j++) acc[i][j] = 0ull;

    #pragma unroll 8
    for (int m = 0; m < 32; m++) {
        float4 wv = *reinterpret_cast<const float4*>(wp + m * 256);
        u64 w0 = dup2(wv.x), w1 = dup2(wv.y), w2v = dup2(wv.z), w3v = dup2(wv.w);
        const u64* hq = reinterpret_cast<const u64*>(hp + m * 64);
        #pragma unroll
        for (int i = 0; i < 8; i++) {
            u64 hv = hq[i];
            acc[i][0] = f2fma(hv, w0,  acc[i][0]);
            acc[i][1] = f2fma(hv, w1,  acc[i][1]);
            acc[i][2] = f2fma(hv, w2v, acc[i][2]);
            acc[i][3] = f2fma(hv, w3v, acc[i][3]);
        }
    }

    #pragma unroll
    for (int i = 0; i < 8; i++) {
        float2 a0 = *reinterpret_cast<float2*>(&acc[i][0]);
        float2 a1 = *reinterpret_cast<float2*>(&acc[i][1]);
        float2 a2 = *reinterpret_cast<float2*>(&acc[i][2]);
        float2 a3 = *reinterpret_cast<float2*>(&acc[i][3]);
        int ee = eb0 + eg * 16 + 2 * i;
        if (ee < E_TOT)
            *reinterpret_cast<float4*>(g_R + (size_t)ee * 11264 + f * 256 + p0) =
                make_float4(a0.x, a1.x, a2.x, a3.x);
        if (ee + 1 < E_TOT)
            *reinterpret_cast<float4*>(g_R + (size_t)(ee + 1) * 11264 + f * 256 + p0) =
                make_float4(a0.y, a1.y, a2.y, a3.y);
    }
}

// ---------------------------------------------------------------------------
// conv kernel v7: skewed pipeline + register-pipelined R (no rr smem).
// EB=8, 128 threads, thread=(e2,co). smem = bb[2]+Ts[2] = 34.8 KB -> 5 blk/SM.
//
// Iteration f: bar -> issue bb(f+1) -> LDG rvB=R(f) -> step4(f-1, rvA) ->
//              step2(f) -> rvA=rvB.
// R(f) LDGs have a full iteration (~1.5K cyc) to land via scoreboard.
// ---------------------------------------------------------------------------
__global__ void __launch_bounds__(128, 5) conv_main_kernel(
    const float* __restrict__ features,  // [E,16,16]
    const float* __restrict__ basis,     // [E,16,44,16]
    float*       __restrict__ out)       // [E,16,16]
{
    extern __shared__ float sm[];
    float* bb = sm;                      // 2*2176
    float* Ts = sm + 2 * BUF;            // 2*2176  -> 8704 floats (34816 B)

    const int t  = threadIdx.x;
    const int e0 = blockIdx.x * EB;
    const int e2 = t >> 4;               // edge (0..7)
    const int co = t & 15;               // ci for step2, co for step4

    // ---- cp.async roles: 4 bb chunks, chunk q = t + 128*j ----
    const float* bsrc[4];
    u32 bdst[4];
    const u32 bb_u = smem_u32(bb);
    #pragma unroll
    for (int j = 0; j < 4; j++) {
        int q  = t + 128 * j;
        int qe = q >> 6;
        int qo = (q & 63) * 4;
        int qi = qo >> 4;
        int qz = qo & 15;
        bsrc[j] = basis + (size_t)(e0 + qe) * 11264 + qi * 704 + qz;   // + f*16
        bdst[j] = bb_u + (qe * STRIDE + qi * 16 + qz) * 4;
    }

    // R stream base: g_R[e0+e2][f*256 + cc*16 + co]
    const float* Rg = g_R + (size_t)(e0 + e2) * 11264 + co;

    // ---- features row (e2, co) in registers ----
    float fF[16];
    {
        const float4* fp = reinterpret_cast<const float4*>(
            features + ((size_t)(e0 + e2) * 16 + co) * 16);
        #pragma unroll
        for (int k = 0; k < 4; k++) {
            float4 v = fp[k];
            fF[4*k] = v.x; fF[4*k+1] = v.y; fF[4*k+2] = v.z; fF[4*k+3] = v.w;
        }
    }

    u64 accO[8];
    #pragma unroll
    for (int i = 0; i < 8; i++) accO[i] = 0ull;

    float rvA[16], rvB[16];

    auto do_step2 = [&](int f) {
        u64 tacc[8];
        #pragma unroll
        for (int i = 0; i < 8; i++) tacc[i] = 0ull;
        const float* bp = bb + (f & 1) * BUF + e2 * STRIDE;
        #pragma unroll 4
        for (int in = 0; in < 16; in++) {
            const float* q = bp + in * 16;
            ulonglong2 x0 = *reinterpret_cast<const ulonglong2*>(q);
            ulonglong2 x1 = *reinterpret_cast<const ulonglong2*>(q + 4);
            ulonglong2 x2 = *reinterpret_cast<const ulonglong2*>(q + 8);
            ulonglong2 x3 = *reinterpret_cast<const ulonglong2*>(q + 12);
            u64 fd = dup2(fF[in]);
            tacc[0] = f2fma(fd, x0.x, tacc[0]); tacc[1] = f2fma(fd, x0.y, tacc[1]);
            tacc[2] = f2fma(fd, x1.x, tacc[2]); tacc[3] = f2fma(fd, x1.y, tacc[3]);
            tacc[4] = f2fma(fd, x2.x, tacc[4]); tacc[5] = f2fma(fd, x2.y, tacc[5]);
            tacc[6] = f2fma(fd, x3.x, tacc[6]); tacc[7] = f2fma(fd, x3.y, tacc[7]);
        }
        float* ta = Ts + (f & 1) * BUF + e2 * STRIDE + co * 16;
        const int sw = co & 3;
        #pragma unroll
        for (int k = 0; k < 4; k++) {
            int kk = k ^ sw;
            *reinterpret_cast<ulonglong2*>(ta + (kk << 2)) =
                make_ulonglong2(tacc[2*k], tacc[2*k+1]);
        }
    };

    auto do_step4 = [&](int f, const float* rv) {
        const float* Te = Ts + (f & 1) * BUF + e2 * STRIDE;
        #pragma unroll 4
        for (int cc = 0; cc < 16; cc++) {
            u64 rd = dup2(rv[cc]);
            const float* tc = Te + cc * 16;
            const int sw = cc & 3;
            ulonglong2 x0 = *reinterpret_cast<const ulonglong2*>(tc + ((0 ^ sw) << 2));
            ulonglong2 x1 = *reinterpret_cast<const ulonglong2*>(tc + ((1 ^ sw) << 2));
            ulonglong2 x2 = *reinterpret_cast<const ulonglong2*>(tc + ((2 ^ sw) << 2));
            ulonglong2 x3 = *reinterpret_cast<const ulonglong2*>(tc + ((3 ^ sw) << 2));
            accO[0] = f2fma(rd, x0.x, accO[0]); accO[1] = f2fma(rd, x0.y, accO[1]);
            accO[2] = f2fma(rd, x1.x, accO[2]); accO[3] = f2fma(rd, x1.y, accO[3]);
            accO[4] = f2fma(rd, x2.x, accO[4]); accO[5] = f2fma(rd, x2.y, accO[5]);
            accO[6] = f2fma(rd, x3.x, accO[6]); accO[7] = f2fma(rd, x3.y, accO[7]);
        }
    };

    // ---- prologue ----
    #pragma unroll
    for (int j = 0; j < 4; j++) cp16(bdst[j], bsrc[j]);
    cp_commit();

    // rvA = R(0)
    #pragma unroll
    for (int cc = 0; cc < 16; cc++) rvA[cc] = Rg[cc * 16];

    cp_wait<0>();
    __syncthreads();
    #pragma unroll
    for (int j = 0; j < 4; j++) cp16(bdst[j] + (BUF * 4), bsrc[j] + 16);
    cp_commit();
    do_step2(0);

    // main loop: f = 1..43 : load rvB=R(f); step4(f-1, rvA); step2(f)
    for (int f = 1; f < FREQ; f++) {
        cp_wait<0>();
        __syncthreads();   // bb(f) visible; Ts(f-1) ready; buffer tenants retired

        if (f + 1 < FREQ) {
            const u32 boff = ((f + 1) & 1) * (BUF * 4);
            #pragma unroll
            for (int j = 0; j < 4; j++) cp16(bdst[j] + boff, bsrc[j] + (f + 1) * 16);
            cp_commit();
        }

        // issue R(f) loads early; consumed by step4(f) next iteration
        {
            const float* rp = Rg + f * 256;
            #pragma unroll
            for (int cc = 0; cc < 16; cc++) rvB[cc] = rp[cc * 16];
        }

        do_step4(f - 1, rvA);
        do_step2(f);

        #pragma unroll
        for (int cc = 0; cc < 16; cc++) rvA[cc] = rvB[cc];
    }

    // tail
    cp_wait<0>();
    __syncthreads();
    do_step4(FREQ - 1, rvA);

    // ---- epilogue: out[e2][co][0..15] ----
    {
        float* op = out + ((size_t)(e0 + e2) * 16 + co) * 16;
        *reinterpret_cast<ulonglong2*>(op)      = make_ulonglong2(accO[0], accO[1]);
        *reinterpret_cast<ulonglong2*>(op + 4)  = make_ulonglong2(accO[2], accO[3]);
        *reinterpret_cast<ulonglong2*>(op + 8)  = make_ulonglong2(accO[4], accO[5]);
        *reinterpret_cast<ulonglong2*>(op + 12) = make_ulonglong2(accO[6], accO[7]);
    }
}

// ---------------------------------------------------------------------------
extern "C" void kernel_launch(void* const* d_in, const int* in_sizes, int n_in,
                              void* d_out, int out_size)
{
    const float* features = (const float*)d_in[0];
    const float* inv      = (const float*)d_in[1];
    const float* basis    = (const float*)d_in[2];
    const float* w1  = (const float*)d_in[3];
    const float* b1  = (const float*)d_in[4];
    const float* g1  = (const float*)d_in[5];
    const float* be1 = (const float*)d_in[6];
    const float* w2  = (const float*)d_in[7];
    const float* b2  = (const float*)d_in[8];
    const float* g2  = (const float*)d_in[9];
    const float* be2 = (const float*)d_in[10];
    const float* w3  = (const float*)d_in[11];
    float* out = (float*)d_out;

    const int smem_bytes = (4 * BUF) * 4;   // 34816
    cudaFuncSetAttribute(conv_main_kernel,
                         cudaFuncAttributeMaxDynamicSharedMemorySize, smem_bytes);

    prep_kernel<<<MLP_BLOCKS + W3T_BLOCKS, 256>>>(inv, w1, b1, g1, be1,
                                                  w2, b2, g2, be2, w3);
    rw_gemm_kernel<<<GEB * FREQ, 256>>>();
    conv_main_kernel<<<NBLK, 128, smem_bytes>>>(features, basis, out);
}

// round 16
// speedup vs baseline: 1.1414x; 1.1414x over previous
#include <cuda_runtime.h>
#include <cuda_bf16.h>

typedef unsigned long long u64;
typedef unsigned int u32;

#define E_TOT   10000
#define FREQ    44
#define EB      8
#define NBLK    (E_TOT / EB)               // 1250, exact
#define LN_EPS  1e-5f

#define MLP_BLOCKS  (E_TOT / 8)                     // 1250
#define W3T_BLOCKS  ((FREQ * 32 * 256 + 255) / 256) // 1408

#define GE      64
#define GEB     ((E_TOT + GE - 1) / GE)             // 157

#define STRIDE  272                        // floats per edge-row (e-offset = 16 banks)
#define BUF     (EB * STRIDE)              // 2176 floats per slice buffer

// scratch
__device__ float g_h[E_TOT * 32];
__device__ float g_w3t[FREQ * 32 * 256];            // [f][m][p], p = ci*16+co
__device__ float g_R[(size_t)E_TOT * FREQ * 256];   // [e][f][p]  (~450 MB)

// ---------------------------------------------------------------------------
__device__ __forceinline__ u64 f2fma(u64 a, u64 b, u64 c) {
    u64 d;
    asm("fma.rn.f32x2 %0, %1, %2, %3;" : "=l"(d) : "l"(a), "l"(b), "l"(c));
    return d;
}
__device__ __forceinline__ u64 dup2(float x) {
    u64 d;
    asm("mov.b64 %0, {%1, %1};" : "=l"(d) : "f"(x));
    return d;
}
__device__ __forceinline__ u32 smem_u32(const void* p) {
    u32 a;
    asm("{ .reg .u64 t; cvta.to.shared.u64 t, %1; cvt.u32.u64 %0, t; }" : "=r"(a) : "l"(p));
    return a;
}
__device__ __forceinline__ void cp16(u32 s, const float* g) {
    asm volatile("cp.async.cg.shared.global [%0], [%1], 16;\n" :: "r"(s), "l"(g));
}
__device__ __forceinline__ void cp_commit() {
    asm volatile("cp.async.commit_group;\n");
}
template <int N>
__device__ __forceinline__ void cp_wait() {
    asm volatile("cp.async.wait_group %0;\n" :: "n"(N));
}

// ---------------------------------------------------------------------------
// dummy kernel: shifts the ncu -s window so conv_main_kernel gets profiled
// ---------------------------------------------------------------------------
__global__ void dummy_kernel() {}

// ---------------------------------------------------------------------------
// prep kernel: MLP (first MLP_BLOCKS blocks) + w3 transpose (rest)
// ---------------------------------------------------------------------------
__device__ __forceinline__ float ln_relu_32(float y, float gamma, float beta) {
    float s = y, q = y * y;
    #pragma unroll
    for (int d = 16; d > 0; d >>= 1) {
        s += __shfl_xor_sync(0xffffffffu, s, d);
        q += __shfl_xor_sync(0xffffffffu, q, d);
    }
    float mean = s * (1.0f / 32.0f);
    float var  = q * (1.0f / 32.0f) - mean * mean;
    float r = rsqrtf(var + LN_EPS);
    float v = (y - mean) * r * gamma + beta;
    return fmaxf(v, 0.0f);
}

__global__ void __launch_bounds__(256) prep_kernel(
    const float* __restrict__ inv,
    const float* __restrict__ w1, const float* __restrict__ b1,
    const float* __restrict__ g1, const float* __restrict__ be1,
    const float* __restrict__ w2, const float* __restrict__ b2,
    const float* __restrict__ g2, const float* __restrict__ be2,
    const float* __restrict__ w3)
{
    if (blockIdx.x >= MLP_BLOCKS) {
        int idx = (blockIdx.x - MLP_BLOCKS) * 256 + threadIdx.x;
        if (idx < FREQ * 32 * 256) {
            int p = idx & 255;
            int m = (idx >> 8) & 31;
            int f = idx >> 13;
            int row = (p & 15) * 704 + (p >> 4) * 44 + f;
            g_w3t[idx] = w3[row * 32 + m];
        }
        return;
    }

    __shared__ float w1_s[32 * 16];
    __shared__ float w2_s[32 * 32];
    __shared__ float p_s[6 * 32];

    int tid = threadIdx.x;
    for (int i = tid; i < 512;  i += 256) w1_s[i] = w1[i];
    for (int i = tid; i < 1024; i += 256) w2_s[i] = w2[i];
    if (tid < 32) {
        p_s[tid]       = b1[tid];
        p_s[32  + tid] = g1[tid];
        p_s[64  + tid] = be1[tid];
        p_s[96  + tid] = b2[tid];
        p_s[128 + tid] = g2[tid];
        p_s[160 + tid] = be2[tid];
    }
    __syncthreads();

    int w = tid >> 5;
    int m = tid & 31;
    int e = blockIdx.x * 8 + w;

    float xv = (m < 16) ? inv[e * 16 + m] : 0.0f;

    float y = p_s[m];
    #pragma unroll
    for (int in = 0; in < 16; in++)
        y = fmaf(__shfl_sync(0xffffffffu, xv, in), w1_s[m * 16 + in], y);
    y = ln_relu_32(y, p_s[32 + m], p_s[64 + m]);

    float y2 = p_s[96 + m];
    #pragma unroll
    for (int k = 0; k < 32; k++)
        y2 = fmaf(__shfl_sync(0xffffffffu, y, k), w2_s[m * 32 + k], y2);
    y2 = ln_relu_32(y2, p_s[128 + m], p_s[160 + m]);

    g_h[e * 32 + m] = y2;
}

// ---------------------------------------------------------------------------
// rw GEMM kernel: g_R[e][f][p] = sum_m g_h[e][m] * g_w3t[f][m][p]
// ---------------------------------------------------------------------------
__global__ void __launch_bounds__(256) rw_gemm_kernel()
{
    __shared__ float hs2[32 * 64];    // [m][e]

    const int t   = threadIdx.x;
    const int f   = blockIdx.x % FREQ;
    const int eb0 = (blockIdx.x / FREQ) * GE;

    #pragma unroll
    for (int i = 0; i < 8; i++) {
        int idx = t + i * 256;
        int e = idx >> 5, m = idx & 31;
        hs2[m * 64 + e] = (eb0 + e < E_TOT) ? g_h[(eb0 + e) * 32 + m] : 0.0f;
    }
    __syncthreads();

    const int p0 = (t & 63) * 4;
    const int eg = t >> 6;

    const float* wp = g_w3t + (size_t)f * 8192 + p0;
    const float* hp = hs2 + eg * 16;

    u64 acc[8][4];
    #pragma unroll
    for (int i = 0; i < 8; i++)
        #pragma unroll
        for (int j = 0; j < 4; j++) acc[i][j] = 0ull;

    #pragma unroll 8
    for (int m = 0; m < 32; m++) {
        float4 wv = *reinterpret_cast<const float4*>(wp + m * 256);
        u64 w0 = dup2(wv.x), w1 = dup2(wv.y), w2v = dup2(wv.z), w3v = dup2(wv.w);
        const u64* hq = reinterpret_cast<const u64*>(hp + m * 64);
        #pragma unroll
        for (int i = 0; i < 8; i++) {
            u64 hv = hq[i];
            acc[i][0] = f2fma(hv, w0,  acc[i][0]);
            acc[i][1] = f2fma(hv, w1,  acc[i][1]);
            acc[i][2] = f2fma(hv, w2v, acc[i][2]);
            acc[i][3] = f2fma(hv, w3v, acc[i][3]);
        }
    }

    #pragma unroll
    for (int i = 0; i < 8; i++) {
        float2 a0 = *reinterpret_cast<float2*>(&acc[i][0]);
        float2 a1 = *reinterpret_cast<float2*>(&acc[i][1]);
        float2 a2 = *reinterpret_cast<float2*>(&acc[i][2]);
        float2 a3 = *reinterpret_cast<float2*>(&acc[i][3]);
        int ee = eb0 + eg * 16 + 2 * i;
        if (ee < E_TOT)
            *reinterpret_cast<float4*>(g_R + (size_t)ee * 11264 + f * 256 + p0) =
                make_float4(a0.x, a1.x, a2.x, a3.x);
        if (ee + 1 < E_TOT)
            *reinterpret_cast<float4*>(g_R + (size_t)(ee + 1) * 11264 + f * 256 + p0) =
                make_float4(a0.y, a1.y, a2.y, a3.y);
    }
}

// ---------------------------------------------------------------------------
// conv kernel v6 (r14 WIN structure): skewed software pipeline, EB=8,
// 128 threads, thread=(e2,co). One __syncthreads per f; step4(f-1)+step2(f)
// run back-to-back on disjoint buffers. Full unroll in both steps.
// ---------------------------------------------------------------------------
__global__ void __launch_bounds__(128, 4) conv_main_kernel(
    const float* __restrict__ features,  // [E,16,16]
    const float* __restrict__ basis,     // [E,16,44,16]
    float*       __restrict__ out)       // [E,16,16]
{
    extern __shared__ float sm[];
    float* bb = sm;                      // 2*2176
    float* rr = sm + 2 * BUF;            // 2*2176
    float* Ts = sm + 4 * BUF;            // 2*2176  -> 13056 floats (52224 B)

    const int t  = threadIdx.x;
    const int e0 = blockIdx.x * EB;
    const int e2 = t >> 4;               // edge (0..7)
    const int co = t & 15;               // ci for step2, co for step4

    // ---- cp.async roles: 4 bb + 4 rr chunks, chunk q = t + 128*j ----
    const float* bsrc[4];
    const float* rsrc[4];
    u32 bdst[4], rdst[4];
    const u32 bb_u = smem_u32(bb);
    const u32 rr_u = smem_u32(rr);
    #pragma unroll
    for (int j = 0; j < 4; j++) {
        int q  = t + 128 * j;
        int qe = q >> 6;
        int qo = (q & 63) * 4;
        int qi = qo >> 4;
        int qz = qo & 15;
        bsrc[j] = basis + (size_t)(e0 + qe) * 11264 + qi * 704 + qz;   // + f*16
        rsrc[j] = g_R   + (size_t)(e0 + qe) * 11264 + qo;              // + f*256
        bdst[j] = bb_u + (qe * STRIDE + qi * 16 + qz) * 4;
        rdst[j] = rr_u + (qe * STRIDE + qo) * 4;
    }

    // ---- features row (e2, co) in registers ----
    float fF[16];
    {
        const float4* fp = reinterpret_cast<const float4*>(
            features + ((size_t)(e0 + e2) * 16 + co) * 16);
        #pragma unroll
        for (int k = 0; k < 4; k++) {
            float4 v = fp[k];
            fF[4*k] = v.x; fF[4*k+1] = v.y; fF[4*k+2] = v.z; fF[4*k+3] = v.w;
        }
    }

    u64 accO[8];
    #pragma unroll
    for (int i = 0; i < 8; i++) accO[i] = 0ull;

    auto do_step2 = [&](int f) {
        u64 tacc[8];
        #pragma unroll
        for (int i = 0; i < 8; i++) tacc[i] = 0ull;
        const float* bp = bb + (f & 1) * BUF + e2 * STRIDE;
        #pragma unroll
        for (int in = 0; in < 16; in++) {
            const float* q = bp + in * 16;
            ulonglong2 x0 = *reinterpret_cast<const ulonglong2*>(q);
            ulonglong2 x1 = *reinterpret_cast<const ulonglong2*>(q + 4);
            ulonglong2 x2 = *reinterpret_cast<const ulonglong2*>(q + 8);
            ulonglong2 x3 = *reinterpret_cast<const ulonglong2*>(q + 12);
            u64 fd = dup2(fF[in]);
            tacc[0] = f2fma(fd, x0.x, tacc[0]); tacc[1] = f2fma(fd, x0.y, tacc[1]);
            tacc[2] = f2fma(fd, x1.x, tacc[2]); tacc[3] = f2fma(fd, x1.y, tacc[3]);
            tacc[4] = f2fma(fd, x2.x, tacc[4]); tacc[5] = f2fma(fd, x2.y, tacc[5]);
            tacc[6] = f2fma(fd, x3.x, tacc[6]); tacc[7] = f2fma(fd, x3.y, tacc[7]);
        }
        float* ta = Ts + (f & 1) * BUF + e2 * STRIDE + co * 16;
        const int sw = co & 3;
        #pragma unroll
        for (int k = 0; k < 4; k++) {
            int kk = k ^ sw;
            *reinterpret_cast<ulonglong2*>(ta + (kk << 2)) =
                make_ulonglong2(tacc[2*k], tacc[2*k+1]);
        }
    };

    auto do_step4 = [&](int f) {
        const float* Te = Ts + (f & 1) * BUF + e2 * STRIDE;
        const float* Re = rr + (f & 1) * BUF + e2 * STRIDE;
        #pragma unroll
        for (int cc = 0; cc < 16; cc++) {
            float rv = Re[cc * 16 + co];
            u64 rd = dup2(rv);
            const float* tc = Te + cc * 16;
            const int sw = cc & 3;
            ulonglong2 x0 = *reinterpret_cast<const ulonglong2*>(tc + ((0 ^ sw) << 2));
            ulonglong2 x1 = *reinterpret_cast<const ulonglong2*>(tc + ((1 ^ sw) << 2));
            ulonglong2 x2 = *reinterpret_cast<const ulonglong2*>(tc + ((2 ^ sw) << 2));
            ulonglong2 x3 = *reinterpret_cast<const ulonglong2*>(tc + ((3 ^ sw) << 2));
            accO[0] = f2fma(rd, x0.x, accO[0]); accO[1] = f2fma(rd, x0.y, accO[1]);
            accO[2] = f2fma(rd, x1.x, accO[2]); accO[3] = f2fma(rd, x1.y, accO[3]);
            accO[4] = f2fma(rd, x2.x, accO[4]); accO[5] = f2fma(rd, x2.y, accO[5]);
            accO[6] = f2fma(rd, x3.x, accO[6]); accO[7] = f2fma(rd, x3.y, accO[7]);
        }
    };

    // ---- prologue: stage bb slice 0 ----
    #pragma unroll
    for (int j = 0; j < 4; j++) cp16(bdst[j], bsrc[j]);
    cp_commit();

    // iter 0: step2(0); issue bb(1) + rr(0)
    cp_wait<0>();
    __syncthreads();
    #pragma unroll
    for (int j = 0; j < 4; j++) cp16(bdst[j] + (BUF * 4), bsrc[j] + 16);
    #pragma unroll
    for (int j = 0; j < 4; j++) cp16(rdst[j], rsrc[j]);
    cp_commit();
    do_step2(0);

    // main loop: iter f = 1..43 : step4(f-1) + step2(f)
    for (int f = 1; f < FREQ; f++) {
        cp_wait<0>();
        __syncthreads();   // Ts(f-1) ready; bb(f), rr(f-1) visible; tenants retired

        {
            const u32 boff = ((f + 1) & 1) * (BUF * 4);
            const u32 roff = (f & 1) * (BUF * 4);
            if (f + 1 < FREQ) {
                #pragma unroll
                for (int j = 0; j < 4; j++) cp16(bdst[j] + boff, bsrc[j] + (f + 1) * 16);
            }
            #pragma unroll
            for (int j = 0; j < 4; j++) cp16(rdst[j] + roff, rsrc[j] + f * 256);
            cp_commit();
        }

        do_step4(f - 1);
        do_step2(f);
    }

    // tail: step4(43)
    cp_wait<0>();
    __syncthreads();
    do_step4(FREQ - 1);

    // ---- epilogue: out[e2][co][0..15] ----
    {
        float* op = out + ((size_t)(e0 + e2) * 16 + co) * 16;
        *reinterpret_cast<ulonglong2*>(op)      = make_ulonglong2(accO[0], accO[1]);
        *reinterpret_cast<ulonglong2*>(op + 4)  = make_ulonglong2(accO[2], accO[3]);
        *reinterpret_cast<ulonglong2*>(op + 8)  = make_ulonglong2(accO[4], accO[5]);
        *reinterpret_cast<ulonglong2*>(op + 12) = make_ulonglong2(accO[6], accO[7]);
    }
}

// ---------------------------------------------------------------------------
extern "C" void kernel_launch(void* const* d_in, const int* in_sizes, int n_in,
                              void* d_out, int out_size)
{
    const float* features = (const float*)d_in[0];
    const float* inv      = (const float*)d_in[1];
    const float* basis    = (const float*)d_in[2];
    const float* w1  = (const float*)d_in[3];
    const float* b1  = (const float*)d_in[4];
    const float* g1  = (const float*)d_in[5];
    const float* be1 = (const float*)d_in[6];
    const float* w2  = (const float*)d_in[7];
    const float* b2  = (const float*)d_in[8];
    const float* g2  = (const float*)d_in[9];
    const float* be2 = (const float*)d_in[10];
    const float* w3  = (const float*)d_in[11];
    float* out = (float*)d_out;

    const int smem_bytes = (6 * BUF) * 4;   // 52224
    cudaFuncSetAttribute(conv_main_kernel,
                         cudaFuncAttributeMaxDynamicSharedMemorySize, smem_bytes);

    // dummy launches: shift ncu's -s window so conv_main_kernel is profiled
    dummy_kernel<<<1, 32>>>();
    dummy_kernel<<<1, 32>>>();

    prep_kernel<<<MLP_BLOCKS + W3T_BLOCKS, 256>>>(inv, w1, b1, g1, be1,
                                                  w2, b2, g2, be2, w3);
    rw_gemm_kernel<<<GEB * FREQ, 256>>>();
    conv_main_kernel<<<NBLK, 128, smem_bytes>>>(features, basis, out);
}

// round 17
// speedup vs baseline: 1.1616x; 1.0177x over previous
#include <cuda_runtime.h>
#include <cuda_bf16.h>

typedef unsigned long long u64;
typedef unsigned int u32;

#define E_TOT   10000
#define FREQ    44
#define EB      8
#define NBLK    (E_TOT / EB)               // 1250, exact
#define LN_EPS  1e-5f

#define MLP_BLOCKS  (E_TOT / 8)                     // 1250
#define W3T_BLOCKS  ((FREQ * 32 * 256 + 255) / 256) // 1408

#define GE      32                                  // edges per gemm block
#define GEB     ((E_TOT + GE - 1) / GE)             // 313

#define STRIDE  272                        // floats per edge-row (e-offset = 16 banks)
#define BUF     (EB * STRIDE)              // 2176 floats per slice buffer

// scratch
__device__ float g_h[E_TOT * 32];
__device__ float g_w3t[FREQ * 32 * 256];            // [f][m][p], p = ci*16+co
__device__ float g_R[(size_t)E_TOT * FREQ * 256];   // [e][f][p]  (~450 MB)

// ---------------------------------------------------------------------------
__device__ __forceinline__ u64 f2fma(u64 a, u64 b, u64 c) {
    u64 d;
    asm("fma.rn.f32x2 %0, %1, %2, %3;" : "=l"(d) : "l"(a), "l"(b), "l"(c));
    return d;
}
__device__ __forceinline__ u64 dup2(float x) {
    u64 d;
    asm("mov.b64 %0, {%1, %1};" : "=l"(d) : "f"(x));
    return d;
}
__device__ __forceinline__ u32 smem_u32(const void* p) {
    u32 a;
    asm("{ .reg .u64 t; cvta.to.shared.u64 t, %1; cvt.u32.u64 %0, t; }" : "=r"(a) : "l"(p));
    return a;
}
__device__ __forceinline__ void cp16(u32 s, const float* g) {
    asm volatile("cp.async.cg.shared.global [%0], [%1], 16;\n" :: "r"(s), "l"(g));
}
__device__ __forceinline__ void cp_commit() {
    asm volatile("cp.async.commit_group;\n");
}
template <int N>
__device__ __forceinline__ void cp_wait() {
    asm volatile("cp.async.wait_group %0;\n" :: "n"(N));
}

// ---------------------------------------------------------------------------
// dummy kernel: positions conv_main_kernel at global launch index 3 (profiled)
// ---------------------------------------------------------------------------
__global__ void dummy_kernel() {}

// ---------------------------------------------------------------------------
// prep kernel: MLP (first MLP_BLOCKS blocks) + w3 transpose (rest)
// ---------------------------------------------------------------------------
__device__ __forceinline__ float ln_relu_32(float y, float gamma, float beta) {
    float s = y, q = y * y;
    #pragma unroll
    for (int d = 16; d > 0; d >>= 1) {
        s += __shfl_xor_sync(0xffffffffu, s, d);
        q += __shfl_xor_sync(0xffffffffu, q, d);
    }
    float mean = s * (1.0f / 32.0f);
    float var  = q * (1.0f / 32.0f) - mean * mean;
    float r = rsqrtf(var + LN_EPS);
    float v = (y - mean) * r * gamma + beta;
    return fmaxf(v, 0.0f);
}

__global__ void __launch_bounds__(256) prep_kernel(
    const float* __restrict__ inv,
    const float* __restrict__ w1, const float* __restrict__ b1,
    const float* __restrict__ g1, const float* __restrict__ be1,
    const float* __restrict__ w2, const float* __restrict__ b2,
    const float* __restrict__ g2, const float* __restrict__ be2,
    const float* __restrict__ w3)
{
    if (blockIdx.x >= MLP_BLOCKS) {
        int idx = (blockIdx.x - MLP_BLOCKS) * 256 + threadIdx.x;
        if (idx < FREQ * 32 * 256) {
            int p = idx & 255;
            int m = (idx >> 8) & 31;
            int f = idx >> 13;
            int row = (p & 15) * 704 + (p >> 4) * 44 + f;
            g_w3t[idx] = w3[row * 32 + m];
        }
        return;
    }

    __shared__ float w1_s[32 * 16];
    __shared__ float w2_s[32 * 32];
    __shared__ float p_s[6 * 32];

    int tid = threadIdx.x;
    for (int i = tid; i < 512;  i += 256) w1_s[i] = w1[i];
    for (int i = tid; i < 1024; i += 256) w2_s[i] = w2[i];
    if (tid < 32) {
        p_s[tid]       = b1[tid];
        p_s[32  + tid] = g1[tid];
        p_s[64  + tid] = be1[tid];
        p_s[96  + tid] = b2[tid];
        p_s[128 + tid] = g2[tid];
        p_s[160 + tid] = be2[tid];
    }
    __syncthreads();

    int w = tid >> 5;
    int m = tid & 31;
    int e = blockIdx.x * 8 + w;

    float xv = (m < 16) ? inv[e * 16 + m] : 0.0f;

    float y = p_s[m];
    #pragma unroll
    for (int in = 0; in < 16; in++)
        y = fmaf(__shfl_sync(0xffffffffu, xv, in), w1_s[m * 16 + in], y);
    y = ln_relu_32(y, p_s[32 + m], p_s[64 + m]);

    float y2 = p_s[96 + m];
    #pragma unroll
    for (int k = 0; k < 32; k++)
        y2 = fmaf(__shfl_sync(0xffffffffu, y, k), w2_s[m * 32 + k], y2);
    y2 = ln_relu_32(y2, p_s[128 + m], p_s[160 + m]);

    g_h[e * 32 + m] = y2;
}

// ---------------------------------------------------------------------------
// rw GEMM kernel v2: g_R[e][f][p] = sum_m g_h[e][m] * g_w3t[f][m][p]
// block = (ebi, f): 32 edges x 256 p. 256 threads = 4 e-groups(8 edges) x
// 64 p-quads. acc[4][4] = 32 regs -> 4 blocks/SM target.
// ---------------------------------------------------------------------------
__global__ void __launch_bounds__(256) rw_gemm_kernel()
{
    __shared__ float hs2[32 * 32];    // [m][e] (32 edges)

    const int t   = threadIdx.x;
    const int f   = blockIdx.x % FREQ;
    const int eb0 = (blockIdx.x / FREQ) * GE;

    #pragma unroll
    for (int i = 0; i < 4; i++) {
        int idx = t + i * 256;
        int e = idx >> 5, m = idx & 31;
        hs2[m * 32 + e] = (eb0 + e < E_TOT) ? g_h[(eb0 + e) * 32 + m] : 0.0f;
    }
    __syncthreads();

    const int p0 = (t & 63) * 4;      // p quad
    const int eg = t >> 6;            // e-group (8 edges)

    const float* wp = g_w3t + (size_t)f * 8192 + p0;
    const float* hp = hs2 + eg * 8;

    u64 acc[4][4];
    #pragma unroll
    for (int i = 0; i < 4; i++)
        #pragma unroll
        for (int j = 0; j < 4; j++) acc[i][j] = 0ull;

    #pragma unroll 8
    for (int m = 0; m < 32; m++) {
        float4 wv = *reinterpret_cast<const float4*>(wp + m * 256);
        u64 w0 = dup2(wv.x), w1 = dup2(wv.y), w2v = dup2(wv.z), w3v = dup2(wv.w);
        const u64* hq = reinterpret_cast<const u64*>(hp + m * 32);
        #pragma unroll
        for (int i = 0; i < 4; i++) {
            u64 hv = hq[i];
            acc[i][0] = f2fma(hv, w0,  acc[i][0]);
            acc[i][1] = f2fma(hv, w1,  acc[i][1]);
            acc[i][2] = f2fma(hv, w2v, acc[i][2]);
            acc[i][3] = f2fma(hv, w3v, acc[i][3]);
        }
    }

    #pragma unroll
    for (int i = 0; i < 4; i++) {
        float2 a0 = *reinterpret_cast<float2*>(&acc[i][0]);
        float2 a1 = *reinterpret_cast<float2*>(&acc[i][1]);
        float2 a2 = *reinterpret_cast<float2*>(&acc[i][2]);
        float2 a3 = *reinterpret_cast<float2*>(&acc[i][3]);
        int ee = eb0 + eg * 8 + 2 * i;
        if (ee < E_TOT)
            *reinterpret_cast<float4*>(g_R + (size_t)ee * 11264 + f * 256 + p0) =
                make_float4(a0.x, a1.x, a2.x, a3.x);
        if (ee + 1 < E_TOT)
            *reinterpret_cast<float4*>(g_R + (size_t)(ee + 1) * 11264 + f * 256 + p0) =
                make_float4(a0.y, a1.y, a2.y, a3.y);
    }
}

// ---------------------------------------------------------------------------
// conv kernel (r14/r16 WIN structure, unchanged): skewed software pipeline,
// EB=8, 128 threads, thread=(e2,co). One __syncthreads per f.
// ---------------------------------------------------------------------------
__global__ void __launch_bounds__(128, 4) conv_main_kernel(
    const float* __restrict__ features,  // [E,16,16]
    const float* __restrict__ basis,     // [E,16,44,16]
    float*       __restrict__ out)       // [E,16,16]
{
    extern __shared__ float sm[];
    float* bb = sm;                      // 2*2176
    float* rr = sm + 2 * BUF;            // 2*2176
    float* Ts = sm + 4 * BUF;            // 2*2176  -> 13056 floats (52224 B)

    const int t  = threadIdx.x;
    const int e0 = blockIdx.x * EB;
    const int e2 = t >> 4;               // edge (0..7)
    const int co = t & 15;               // ci for step2, co for step4

    const float* bsrc[4];
    const float* rsrc[4];
    u32 bdst[4], rdst[4];
    const u32 bb_u = smem_u32(bb);
    const u32 rr_u = smem_u32(rr);
    #pragma unroll
    for (int j = 0; j < 4; j++) {
        int q  = t + 128 * j;
        int qe = q >> 6;
        int qo = (q & 63) * 4;
        int qi = qo >> 4;
        int qz = qo & 15;
        bsrc[j] = basis + (size_t)(e0 + qe) * 11264 + qi * 704 + qz;   // + f*16
        rsrc[j] = g_R   + (size_t)(e0 + qe) * 11264 + qo;              // + f*256
        bdst[j] = bb_u + (qe * STRIDE + qi * 16 + qz) * 4;
        rdst[j] = rr_u + (qe * STRIDE + qo) * 4;
    }

    float fF[16];
    {
        const float4* fp = reinterpret_cast<const float4*>(
            features + ((size_t)(e0 + e2) * 16 + co) * 16);
        #pragma unroll
        for (int k = 0; k < 4; k++) {
            float4 v = fp[k];
            fF[4*k] = v.x; fF[4*k+1] = v.y; fF[4*k+2] = v.z; fF[4*k+3] = v.w;
        }
    }

    u64 accO[8];
    #pragma unroll
    for (int i = 0; i < 8; i++) accO[i] = 0ull;

    auto do_step2 = [&](int f) {
        u64 tacc[8];
        #pragma unroll
        for (int i = 0; i < 8; i++) tacc[i] = 0ull;
        const float* bp = bb + (f & 1) * BUF + e2 * STRIDE;
        #pragma unroll
        for (int in = 0; in < 16; in++) {
            const float* q = bp + in * 16;
            ulonglong2 x0 = *reinterpret_cast<const ulonglong2*>(q);
            ulonglong2 x1 = *reinterpret_cast<const ulonglong2*>(q + 4);
            ulonglong2 x2 = *reinterpret_cast<const ulonglong2*>(q + 8);
            ulonglong2 x3 = *reinterpret_cast<const ulonglong2*>(q + 12);
            u64 fd = dup2(fF[in]);
            tacc[0] = f2fma(fd, x0.x, tacc[0]); tacc[1] = f2fma(fd, x0.y, tacc[1]);
            tacc[2] = f2fma(fd, x1.x, tacc[2]); tacc[3] = f2fma(fd, x1.y, tacc[3]);
            tacc[4] = f2fma(fd, x2.x, tacc[4]); tacc[5] = f2fma(fd, x2.y, tacc[5]);
            tacc[6] = f2fma(fd, x3.x, tacc[6]); tacc[7] = f2fma(fd, x3.y, tacc[7]);
        }
        float* ta = Ts + (f & 1) * BUF + e2 * STRIDE + co * 16;
        const int sw = co & 3;
        #pragma unroll
        for (int k = 0; k < 4; k++) {
            int kk = k ^ sw;
            *reinterpret_cast<ulonglong2*>(ta + (kk << 2)) =
                make_ulonglong2(tacc[2*k], tacc[2*k+1]);
        }
    };

    auto do_step4 = [&](int f) {
        const float* Te = Ts + (f & 1) * BUF + e2 * STRIDE;
        const float* Re = rr + (f & 1) * BUF + e2 * STRIDE;
        #pragma unroll
        for (int cc = 0; cc < 16; cc++) {
            float rv = Re[cc * 16 + co];
            u64 rd = dup2(rv);
            const float* tc = Te + cc * 16;
            const int sw = cc & 3;
            ulonglong2 x0 = *reinterpret_cast<const ulonglong2*>(tc + ((0 ^ sw) << 2));
            ulonglong2 x1 = *reinterpret_cast<const ulonglong2*>(tc + ((1 ^ sw) << 2));
            ulonglong2 x2 = *reinterpret_cast<const ulonglong2*>(tc + ((2 ^ sw) << 2));
            ulonglong2 x3 = *reinterpret_cast<const ulonglong2*>(tc + ((3 ^ sw) << 2));
            accO[0] = f2fma(rd, x0.x, accO[0]); accO[1] = f2fma(rd, x0.y, accO[1]);
            accO[2] = f2fma(rd, x1.x, accO[2]); accO[3] = f2fma(rd, x1.y, accO[3]);
            accO[4] = f2fma(rd, x2.x, accO[4]); accO[5] = f2fma(rd, x2.y, accO[5]);
            accO[6] = f2fma(rd, x3.x, accO[6]); accO[7] = f2fma(rd, x3.y, accO[7]);
        }
    };

    // ---- prologue: stage bb slice 0 ----
    #pragma unroll
    for (int j = 0; j < 4; j++) cp16(bdst[j], bsrc[j]);
    cp_commit();

    cp_wait<0>();
    __syncthreads();
    #pragma unroll
    for (int j = 0; j < 4; j++) cp16(bdst[j] + (BUF * 4), bsrc[j] + 16);
    #pragma unroll
    for (int j = 0; j < 4; j++) cp16(rdst[j], rsrc[j]);
    cp_commit();
    do_step2(0);

    for (int f = 1; f < FREQ; f++) {
        cp_wait<0>();
        __syncthreads();

        {
            const u32 boff = ((f + 1) & 1) * (BUF * 4);
            const u32 roff = (f & 1) * (BUF * 4);
            if (f + 1 < FREQ) {
                #pragma unroll
                for (int j = 0; j < 4; j++) cp16(bdst[j] + boff, bsrc[j] + (f + 1) * 16);
            }
            #pragma unroll
            for (int j = 0; j < 4; j++) cp16(rdst[j] + roff, rsrc[j] + f * 256);
            cp_commit();
        }

        do_step4(f - 1);
        do_step2(f);
    }

    cp_wait<0>();
    __syncthreads();
    do_step4(FREQ - 1);

    {
        float* op = out + ((size_t)(e0 + e2) * 16 + co) * 16;
        *reinterpret_cast<ulonglong2*>(op)      = make_ulonglong2(accO[0], accO[1]);
        *reinterpret_cast<ulonglong2*>(op + 4)  = make_ulonglong2(accO[2], accO[3]);
        *reinterpret_cast<ulonglong2*>(op + 8)  = make_ulonglong2(accO[4], accO[5]);
        *reinterpret_cast<ulonglong2*>(op + 12) = make_ulonglong2(accO[6], accO[7]);
    }
}

// ---------------------------------------------------------------------------
extern "C" void kernel_launch(void* const* d_in, const int* in_sizes, int n_in,
                              void* d_out, int out_size)
{
    const float* features = (const float*)d_in[0];
    const float* inv      = (const float*)d_in[1];
    const float* basis    = (const float*)d_in[2];
    const float* w1  = (const float*)d_in[3];
    const float* b1  = (const float*)d_in[4];
    const float* g1  = (const float*)d_in[5];
    const float* be1 = (const float*)d_in[6];
    const float* w2  = (const float*)d_in[7];
    const float* b2  = (const float*)d_in[8];
    const float* g2  = (const float*)d_in[9];
    const float* be2 = (const float*)d_in[10];
    const float* w3  = (const float*)d_in[11];
    float* out = (float*)d_out;

    const int smem_bytes = (6 * BUF) * 4;   // 52224
    cudaFuncSetAttribute(conv_main_kernel,
                         cudaFuncAttributeMaxDynamicSharedMemorySize, smem_bytes);

    // order: prep(0), gemm(1), dummy(2), conv(3) -> ncu window profiles conv
    prep_kernel<<<MLP_BLOCKS + W3T_BLOCKS, 256>>>(inv, w1, b1, g1, be1,
                                                  w2, b2, g2, be2, w3);
    rw_gemm_kernel<<<GEB * FREQ, 256>>>();
    dummy_kernel<<<1, 32>>>();
    conv_main_kernel<<<NBLK, 128, smem_bytes>>>(features, basis, out);
}